// round 1
// baseline (speedup 1.0000x reference)
#include <cuda_runtime.h>
#include <math.h>

#define KC   256
#define D    512
#define BSZ  1024
#define NLOW 130816

#define BM 128
#define BN 128
#define DK 16

// Dense L in [k][d][e] layout (lower-triangular, zeros above diag).
__device__ float g_L[(size_t)KC * D * D];

// ---------------------------------------------------------------------------
// Expand packed L (diags, strict-lower tril row-major) into dense g_L.
// ---------------------------------------------------------------------------
__global__ void build_L_kernel(const float* __restrict__ diags,
                               const float* __restrict__ lower) {
    int i = blockIdx.x * blockDim.x + threadIdx.x;  // < KC*D*D = 67,108,864
    int e  = i & (D - 1);
    int rd = i >> 9;            // k*D + d
    int d  = rd & (D - 1);
    int k  = rd >> 9;
    float v;
    if (e == d) {
        float t = diags[rd];
        v = t * t;
    } else if (e < d) {
        v = lower[k * NLOW + ((d * (d - 1)) >> 1) + e];
    } else {
        v = 0.f;
    }
    g_L[i] = v;
}

// ---------------------------------------------------------------------------
// Main: per (k, b-tile) CTA computes G[b] = || (x_b - w_k) @ L_k ||^2 and
// writes sqrt(G) to out[b, k]. Triangular skip: d-loop starts at e0.
// fp32x2 FFMA2 via inline PTX for 2x fp32 throughput.
// ---------------------------------------------------------------------------
union F2 { float2 f; unsigned long long u; };

__global__ void __launch_bounds__(256, 2)
gml2_main(const float* __restrict__ X, const float* __restrict__ W,
          float* __restrict__ out) {
    const int k   = blockIdx.y;
    const int b0  = blockIdx.x * BM;
    const int tid = threadIdx.x;
    const int tx  = tid & 15;
    const int ty  = tid >> 4;

    __shared__ float Vs[DK][BM + 4];   // transposed (x - w) tile, padded
    __shared__ float Ls[DK][BN];       // L tile (d-rows x e-cols)
    __shared__ float Wrow[D];

    for (int i = tid; i < D; i += 256) Wrow[i] = W[k * D + i];

    float G[8];
#pragma unroll
    for (int i = 0; i < 8; i++) G[i] = 0.f;

    for (int e0 = 0; e0 < D; e0 += BN) {
        F2 acc[8][4];
#pragma unroll
        for (int i = 0; i < 8; i++)
#pragma unroll
            for (int c = 0; c < 4; c++) { acc[i][c].f.x = 0.f; acc[i][c].f.y = 0.f; }

        for (int d0 = e0; d0 < D; d0 += DK) {
            __syncthreads();
            // ---- load X tile (128 rows x DK cols), subtract w, store transposed
            {
                const int q  = tid & 3;       // float4 column chunk within DK
                const int r0 = tid >> 2;      // 0..63
#pragma unroll
                for (int it = 0; it < 2; it++) {
                    const int row = r0 + it * 64;
                    const float4 xv = *reinterpret_cast<const float4*>(
                        &X[(size_t)(b0 + row) * D + d0 + q * 4]);
                    const int dd = d0 + q * 4;
                    Vs[q * 4 + 0][row] = xv.x - Wrow[dd + 0];
                    Vs[q * 4 + 1][row] = xv.y - Wrow[dd + 1];
                    Vs[q * 4 + 2][row] = xv.z - Wrow[dd + 2];
                    Vs[q * 4 + 3][row] = xv.w - Wrow[dd + 3];
                }
            }
            // ---- load L tile (DK rows x 128 cols), direct (coalesced float4)
            {
                const int j  = tid >> 4;      // 0..15 (d row within tile)
                const int e4 = tid & 15;      // float4 col index
                const size_t lbase = ((size_t)(k * D + d0 + j)) * D + e0;
#pragma unroll
                for (int it = 0; it < 2; it++) {
                    const int ec = e4 + it * 16;  // 0..31
                    *reinterpret_cast<float4*>(&Ls[j][ec * 4]) =
                        *reinterpret_cast<const float4*>(&g_L[lbase + ec * 4]);
                }
            }
            __syncthreads();

#pragma unroll
            for (int j = 0; j < DK; j++) {
                const float4 v0 = *reinterpret_cast<const float4*>(&Vs[j][ty * 4]);
                const float4 v1 = *reinterpret_cast<const float4*>(&Vs[j][64 + ty * 4]);
                const float4 l0 = *reinterpret_cast<const float4*>(&Ls[j][tx * 4]);
                const float4 l1 = *reinterpret_cast<const float4*>(&Ls[j][64 + tx * 4]);
                F2 bb[4];
                bb[0].f = make_float2(l0.x, l0.y);
                bb[1].f = make_float2(l0.z, l0.w);
                bb[2].f = make_float2(l1.x, l1.y);
                bb[3].f = make_float2(l1.z, l1.w);
                const float va[8] = {v0.x, v0.y, v0.z, v0.w,
                                     v1.x, v1.y, v1.z, v1.w};
#pragma unroll
                for (int i = 0; i < 8; i++) {
                    F2 aa; aa.f = make_float2(va[i], va[i]);
#pragma unroll
                    for (int c = 0; c < 4; c++) {
                        asm("fma.rn.f32x2 %0, %1, %2, %0;"
                            : "+l"(acc[i][c].u)
                            : "l"(aa.u), "l"(bb[c].u));
                    }
                }
            }
        }
        // ---- fold squared tile into row-norm accumulators
#pragma unroll
        for (int i = 0; i < 8; i++) {
            float s = 0.f;
#pragma unroll
            for (int c = 0; c < 4; c++)
                s += acc[i][c].f.x * acc[i][c].f.x + acc[i][c].f.y * acc[i][c].f.y;
            G[i] += s;
        }
    }

    // ---- reduce partial row norms across the 16 tx lanes (same ty)
#pragma unroll
    for (int i = 0; i < 8; i++) {
#pragma unroll
        for (int m = 8; m >= 1; m >>= 1)
            G[i] += __shfl_xor_sync(0xffffffffu, G[i], m);
    }
    if (tx == 0) {
#pragma unroll
        for (int i = 0; i < 8; i++) {
            const int r = (i < 4) ? (ty * 4 + i) : (64 + ty * 4 + (i - 4));
            out[(size_t)(b0 + r) * KC + k] = sqrtf(G[i]);
        }
    }
}

// ---------------------------------------------------------------------------
extern "C" void kernel_launch(void* const* d_in, const int* in_sizes, int n_in,
                              void* d_out, int out_size) {
    const float* X     = (const float*)d_in[0];  // [1024, 512]
    const float* W     = (const float*)d_in[1];  // [256, 1, 512]
    const float* diags = (const float*)d_in[2];  // [256, 512]
    const float* lower = (const float*)d_in[3];  // [256, 130816]
    float* out = (float*)d_out;                  // [1024, 256]

    build_L_kernel<<<(KC * D * D) / 256, 256>>>(diags, lower);

    dim3 grid(BSZ / BM, KC);
    gml2_main<<<grid, 256>>>(X, W, out);
}

// round 3
// speedup vs baseline: 2.2896x; 2.2896x over previous
#include <cuda_runtime.h>
#include <math.h>
#include <stdint.h>

#define KC   256
#define D    512
#define NLOW 130816

// Dense transposed L (tf32-rounded): g_LT[k][e][d] = L_k[d][e], zero for d<e.
__device__ float g_LT[(size_t)KC * D * D];
// Per-e-block partial squared sums: g_part[j][b][k]
__device__ float g_part[(size_t)4 * 1024 * KC];

__device__ __forceinline__ float to_tf32(float x) {
    float r; asm("cvt.rna.tf32.f32 %0, %1;" : "=f"(r) : "f"(x)); return r;
}
__device__ __forceinline__ uint32_t smem_u32(const void* p) {
    uint32_t a;
    asm("{ .reg .u64 t; cvta.to.shared.u64 t, %1; cvt.u32.u64 %0, t; }"
        : "=r"(a) : "l"(p));
    return a;
}
__device__ __forceinline__ void cpasync16(uint32_t dst, const void* src) {
    asm volatile("cp.async.cg.shared.global [%0], [%1], 16;"
                 :: "r"(dst), "l"(src) : "memory");
}
__device__ __forceinline__ uint32_t ldsf(uint32_t a) {
    uint32_t v; asm("ld.shared.b32 %0, [%1];" : "=r"(v) : "r"(a)); return v;
}

// ---------------------------------------------------------------------------
__global__ void build_LT(const float* __restrict__ diags,
                         const float* __restrict__ lower) {
    size_t i = (size_t)blockIdx.x * 256 + threadIdx.x;
    int d = (int)(i & 511);
    size_t ke = i >> 9;
    int e  = (int)(ke & 511);
    int kk = (int)(ke >> 9);
    float v = 0.f;
    if (d == e) { float t = diags[ke]; v = t * t; }
    else if (d > e) v = lower[(size_t)kk * NLOW + (((size_t)d * (d - 1)) >> 1) + e];
    g_LT[i] = to_tf32(v);
}

// ---------------------------------------------------------------------------
// Main GEMM: per (b-tile, k, e-block) CTA, P = (X-w)@L block, acc sum squares.
// A/B SMEM tiles: 128 rows x 32 cols fp32, row stride 36 floats (144B, pad 4).
// ---------------------------------------------------------------------------
#define AOFF   2048
#define ABUF   18432
#define BOFF   (2048 + 2 * 18432)            /* 38912 */
#define BBUF   18432
#define ROFF   (38912 + 3 * 18432)           /* 94208 */
#define SMEMSZ (94208 + 1024)                /* 95232 */

__global__ void __launch_bounds__(256)
gml2_mma(const float* __restrict__ X, const float* __restrict__ W) {
    extern __shared__ char smem[];
    float* Wsm = (float*)smem;
    const int tid = threadIdx.x;
    const int wid = tid >> 5, lid = tid & 31;
    const int b0 = blockIdx.x * 128;
    const int k  = blockIdx.y;
    const int j  = blockIdx.z;
    const int e0 = j << 7;
    const int nc = 16 - (j << 2);            // K-chunks of 32: d in [e0, 512)

    const uint32_t sbase = smem_u32(smem);
    const uint32_t sA = sbase + AOFF;
    const uint32_t sB = sbase + BOFF;

    const int frow = tid >> 3;               // fill: base row (0..31), +it*32
    const int fc4  = tid & 7;                // fill: float4 column

    for (int i = tid; i < D; i += 256) Wsm[i] = W[(size_t)k * D + i];
    __syncthreads();

    const float* LB = &g_LT[((size_t)k * D + e0) * D];   // [row e][d]

    // ---- prologue: A(0) sync fill; B(0), B(1) cp.async (nc >= 4 always)
    {
        const int d0 = e0;
#pragma unroll
        for (int it = 0; it < 4; ++it) {
            int row = frow + it * 32;
            float4 xv = *(const float4*)&X[(size_t)(b0 + row) * D + d0 + fc4 * 4];
            float4 wv = *(const float4*)&Wsm[d0 + fc4 * 4];
            float4 v;
            v.x = to_tf32(xv.x - wv.x); v.y = to_tf32(xv.y - wv.y);
            v.z = to_tf32(xv.z - wv.z); v.w = to_tf32(xv.w - wv.w);
            *(float4*)(smem + AOFF + row * 144 + fc4 * 16) = v;
        }
    }
#pragma unroll
    for (int p = 0; p < 2; ++p) {
        const int d0 = e0 + p * 32;
#pragma unroll
        for (int it = 0; it < 4; ++it) {
            int row = frow + it * 32;
            cpasync16(sB + p * BBUF + row * 144 + fc4 * 16,
                      LB + (size_t)row * D + d0 + fc4 * 4);
        }
        asm volatile("cp.async.commit_group;" ::: "memory");
    }
    __syncthreads();

    float acc[2][8][4];
#pragma unroll
    for (int mt = 0; mt < 2; ++mt)
#pragma unroll
        for (int nt = 0; nt < 8; ++nt)
#pragma unroll
            for (int q = 0; q < 4; ++q) acc[mt][nt][q] = 0.f;

    const int m0 = (wid & 3) * 32, n0 = (wid >> 2) * 64;
    const int gq = lid >> 2, tg = lid & 3;
    const uint32_t aFrag = sA + (m0 + gq) * 144 + tg * 4;
    const uint32_t bFrag = sB + (n0 + gq) * 144 + tg * 4;

    for (int c = 0; c < nc; ++c) {
        // one group per iteration (possibly empty) -> uniform wait_group 1
        asm volatile("cp.async.wait_group 1;" ::: "memory");
        __syncthreads();

        // issue B(c+2)
        if (c + 2 < nc) {
            const int d0 = e0 + (c + 2) * 32;
            const uint32_t bd = sB + ((c + 2) % 3) * BBUF;
#pragma unroll
            for (int it = 0; it < 4; ++it) {
                int row = frow + it * 32;
                cpasync16(bd + row * 144 + fc4 * 16,
                          LB + (size_t)row * D + d0 + fc4 * 4);
            }
        }
        asm volatile("cp.async.commit_group;" ::: "memory");

        // prefetch A(c+1) globals
        float4 pa[4];
        const int d0n = e0 + (c + 1) * 32;
        if (c + 1 < nc) {
#pragma unroll
            for (int it = 0; it < 4; ++it) {
                int row = frow + it * 32;
                pa[it] = *(const float4*)&X[(size_t)(b0 + row) * D + d0n + fc4 * 4];
            }
        }

        // ---- compute chunk c
        const uint32_t aB = aFrag + (c & 1) * ABUF;
        const uint32_t bB = bFrag + (c % 3) * BBUF;
#pragma unroll
        for (int ks = 0; ks < 4; ++ks) {
            uint32_t a[2][4], b[8][2];
#pragma unroll
            for (int mt = 0; mt < 2; ++mt) {
                const uint32_t base = aB + mt * (16 * 144) + ks * 32;
                a[mt][0] = ldsf(base);
                a[mt][1] = ldsf(base + 8 * 144);
                a[mt][2] = ldsf(base + 16);
                a[mt][3] = ldsf(base + 8 * 144 + 16);
            }
#pragma unroll
            for (int nt = 0; nt < 8; ++nt) {
                const uint32_t base = bB + nt * (8 * 144) + ks * 32;
                b[nt][0] = ldsf(base);
                b[nt][1] = ldsf(base + 16);
            }
#pragma unroll
            for (int mt = 0; mt < 2; ++mt)
#pragma unroll
                for (int nt = 0; nt < 8; ++nt)
                    asm volatile(
                        "mma.sync.aligned.m16n8k8.row.col.f32.tf32.tf32.f32 "
                        "{%0,%1,%2,%3},{%4,%5,%6,%7},{%8,%9},{%0,%1,%2,%3};"
                        : "+f"(acc[mt][nt][0]), "+f"(acc[mt][nt][1]),
                          "+f"(acc[mt][nt][2]), "+f"(acc[mt][nt][3])
                        : "r"(a[mt][0]), "r"(a[mt][1]), "r"(a[mt][2]), "r"(a[mt][3]),
                          "r"(b[nt][0]), "r"(b[nt][1]));
        }

        // store A(c+1) (other buffer; all warps past compute(c-1) via barrier)
        if (c + 1 < nc) {
#pragma unroll
            for (int it = 0; it < 4; ++it) {
                int row = frow + it * 32;
                float4 wv = *(const float4*)&Wsm[d0n + fc4 * 4];
                float4 v;
                v.x = to_tf32(pa[it].x - wv.x); v.y = to_tf32(pa[it].y - wv.y);
                v.z = to_tf32(pa[it].z - wv.z); v.w = to_tf32(pa[it].w - wv.w);
                *(float4*)(smem + AOFF + ((c + 1) & 1) * ABUF + row * 144 + fc4 * 16) = v;
            }
        }
    }

    // ---- epilogue: per-row sum of squares
    float q[4];
#pragma unroll
    for (int mt = 0; mt < 2; ++mt) {
        float s0 = 0.f, s1 = 0.f;
#pragma unroll
        for (int nt = 0; nt < 8; ++nt) {
            s0 += acc[mt][nt][0] * acc[mt][nt][0] + acc[mt][nt][1] * acc[mt][nt][1];
            s1 += acc[mt][nt][2] * acc[mt][nt][2] + acc[mt][nt][3] * acc[mt][nt][3];
        }
        q[mt * 2 + 0] = s0;   // row m0 + 16*mt + gq
        q[mt * 2 + 1] = s1;   // row m0 + 16*mt + gq + 8
    }
#pragma unroll
    for (int i = 0; i < 4; ++i) {
        q[i] += __shfl_xor_sync(0xffffffffu, q[i], 1);
        q[i] += __shfl_xor_sync(0xffffffffu, q[i], 2);
    }
    float* red = (float*)(smem + ROFF);
    __syncthreads();
    if (tg == 0) {
        const int wn = wid >> 2;
        const int r  = m0 + gq;
        red[wn * 128 + r +  0] = q[0];
        red[wn * 128 + r +  8] = q[1];
        red[wn * 128 + r + 16] = q[2];
        red[wn * 128 + r + 24] = q[3];
    }
    __syncthreads();
    if (tid < 128) {
        float s = red[tid] + red[128 + tid];
        g_part[((size_t)j * 1024 + b0 + tid) * KC + k] = s;
    }
}

// ---------------------------------------------------------------------------
__global__ void finalize(float* __restrict__ out) {
    const size_t idx = (size_t)blockIdx.x * 256 + threadIdx.x;  // 1024*256
    float s = g_part[idx] + g_part[262144 + idx] +
              g_part[2 * 262144 + idx] + g_part[3 * 262144 + idx];
    out[idx] = sqrtf(s);
}

// ---------------------------------------------------------------------------
extern "C" void kernel_launch(void* const* d_in, const int* in_sizes, int n_in,
                              void* d_out, int out_size) {
    const float* X     = (const float*)d_in[0];  // [1024, 512]
    const float* W     = (const float*)d_in[1];  // [256, 1, 512]
    const float* diags = (const float*)d_in[2];  // [256, 512]
    const float* lower = (const float*)d_in[3];  // [256, 130816]
    float* out = (float*)d_out;                  // [1024, 256]

    build_LT<<<(KC * D * D) / 256, 256>>>(diags, lower);

    cudaFuncSetAttribute(gml2_mma, cudaFuncAttributeMaxDynamicSharedMemorySize,
                         SMEMSZ);
    dim3 grid(8, KC, 4);
    gml2_mma<<<grid, 256, SMEMSZ>>>(X, W);

    finalize<<<1024, 256>>>(out);
}

// round 4
// speedup vs baseline: 3.9571x; 1.7283x over previous
#include <cuda_runtime.h>
#include <cuda_fp16.h>
#include <math.h>
#include <stdint.h>

#define KC   256
#define D    512
#define NLOW 130816

// Dense transposed L in fp16: g_LTh[k][e][d] = L_k[d][e] (block-lower region).
__device__ __half g_LTh[(size_t)KC * D * D];
// Per-e-block partial squared sums: g_part[j][b][k]
__device__ float g_part[(size_t)4 * 1024 * KC];

__device__ __forceinline__ uint32_t smem_u32(const void* p) {
    uint32_t a;
    asm("{ .reg .u64 t; cvta.to.shared.u64 t, %1; cvt.u32.u64 %0, t; }"
        : "=r"(a) : "l"(p));
    return a;
}
__device__ __forceinline__ void cpasync16(uint32_t dst, const void* src) {
    asm volatile("cp.async.cg.shared.global [%0], [%1], 16;"
                 :: "r"(dst), "l"(src) : "memory");
}
__device__ __forceinline__ uint32_t ldsf(uint32_t a) {
    uint32_t v; asm("ld.shared.b32 %0, [%1];" : "=r"(v) : "r"(a)); return v;
}

// ---------------------------------------------------------------------------
// Build: tiled transpose of packed L into fp16 [k][e][d], 64x64 tiles,
// coalesced reads (e contiguous) and writes (d contiguous).
// Only the 40 tiles per k with dt >= 2*(et>>1) (what the GEMM reads).
// ---------------------------------------------------------------------------
__global__ void __launch_bounds__(256)
build_LTh(const float* __restrict__ diags, const float* __restrict__ lower) {
    __shared__ __half s[64 * 66];
    const int tid = threadIdx.x;
    const int k = blockIdx.x;
    const int y = blockIdx.y;
    int eb, r;
    if (y < 16)      { eb = 0; r = y; }
    else if (y < 28) { eb = 1; r = y - 16; }
    else if (y < 36) { eb = 2; r = y - 28; }
    else             { eb = 3; r = y - 36; }
    const int n  = 8 - 2 * eb;
    const int et = 2 * eb + (r >= n ? 1 : 0);
    const int dt = 2 * eb + (r >= n ? r - n : r);
    const int d0 = dt << 6, e0 = et << 6;

#pragma unroll
    for (int it = 0; it < 16; ++it) {
        const int li = it * 256 + tid;
        const int dl = li >> 6, el = li & 63;
        const int d = d0 + dl, e = e0 + el;
        float v = 0.f;
        if (e == d)      { float t = diags[k * D + d]; v = t * t; }
        else if (e < d)  v = lower[(size_t)k * NLOW + (((size_t)d * (d - 1)) >> 1) + e];
        s[el * 66 + dl] = __float2half_rn(v);
    }
    __syncthreads();
#pragma unroll
    for (int it = 0; it < 8; ++it) {
        const int u = it * 256 + tid;
        const int el = u >> 5, w = u & 31;
        const uint32_t val = *(const uint32_t*)&s[el * 66 + w * 2];
        char* dst = (char*)g_LTh +
                    (((size_t)(k * D + e0 + el)) * D + d0) * 2 + w * 4;
        *(uint32_t*)dst = val;
    }
}

// ---------------------------------------------------------------------------
// Main GEMM (fp16 HMMA): per (b-tile, k, e-block) CTA,
// P = (X - w_k) @ L_k block, accumulate sum of squares per row.
// SMEM tiles: 128 rows x 32 cols fp16, row stride 80 B (conflict-free frags).
// ---------------------------------------------------------------------------
#define AOFF   2048
#define ABUF   10240
#define BOFF   (2048 + 2 * 10240)            /* 22528 */
#define BBUF   10240
#define ROFF   (22528 + 3 * 10240)           /* 53248 */
#define SMEMSZ (53248 + 1024)                /* 54272 */

__global__ void __launch_bounds__(256)
gml2_mma(const float* __restrict__ X, const float* __restrict__ W) {
    extern __shared__ char smem[];
    float* Wsm = (float*)smem;
    const int tid = threadIdx.x;
    const int wid = tid >> 5, lid = tid & 31;
    const int b0 = blockIdx.x * 128;
    const int k  = blockIdx.y;
    const int j  = blockIdx.z;
    const int e0 = j << 7;
    const int nc = 16 - (j << 2);            // K-chunks of 32: d in [e0, 512)

    const uint32_t sbase = smem_u32(smem);
    const uint32_t sA = sbase + AOFF;
    const uint32_t sB = sbase + BOFF;

    for (int i = tid; i < D; i += 256) Wsm[i] = W[(size_t)k * D + i];
    __syncthreads();

    const __half* LB = &g_LTh[((size_t)k * D + e0) * D];   // [row e][d]

    // ---- prologue: A(0) sync fill (fp16); B(0), B(1) cp.async
    {
#pragma unroll
        for (int it = 0; it < 4; ++it) {
            const int idx = it * 256 + tid;          // 128 rows x 8 segs(8B)
            const int row = idx >> 3, seg = idx & 7;
            float4 xv = *(const float4*)&X[(size_t)(b0 + row) * D + e0 + seg * 4];
            float4 wv = *(const float4*)&Wsm[e0 + seg * 4];
            __half2 h0 = __floats2half2_rn(xv.x - wv.x, xv.y - wv.y);
            __half2 h1 = __floats2half2_rn(xv.z - wv.z, xv.w - wv.w);
            uint2 u = make_uint2(*(uint32_t*)&h0, *(uint32_t*)&h1);
            *(uint2*)(smem + AOFF + row * 80 + seg * 8) = u;
        }
    }
#pragma unroll
    for (int p = 0; p < 2; ++p) {
        const int d0 = e0 + p * 32;
#pragma unroll
        for (int it = 0; it < 2; ++it) {
            const int idx = it * 256 + tid;          // 128 rows x 4 segs(16B)
            const int row = idx >> 2, seg = idx & 3;
            cpasync16(sB + p * BBUF + row * 80 + seg * 16,
                      LB + (size_t)row * D + d0 + seg * 8);
        }
        asm volatile("cp.async.commit_group;" ::: "memory");
    }
    __syncthreads();

    float acc[2][8][4];
#pragma unroll
    for (int mt = 0; mt < 2; ++mt)
#pragma unroll
        for (int nt = 0; nt < 8; ++nt)
#pragma unroll
            for (int q = 0; q < 4; ++q) acc[mt][nt][q] = 0.f;

    const int m0 = (wid & 3) * 32, n0 = (wid >> 2) * 64;
    const int gq = lid >> 2, tg = lid & 3;
    const uint32_t aFrag = sA + (m0 + gq) * 80 + tg * 4;
    const uint32_t bFrag = sB + (n0 + gq) * 80 + tg * 4;

    for (int c = 0; c < nc; ++c) {
        asm volatile("cp.async.wait_group 1;" ::: "memory");
        __syncthreads();

        // issue B(c+2)
        if (c + 2 < nc) {
            const int d0 = e0 + (c + 2) * 32;
            const uint32_t bd = sB + ((c + 2) % 3) * BBUF;
#pragma unroll
            for (int it = 0; it < 2; ++it) {
                const int idx = it * 256 + tid;
                const int row = idx >> 2, seg = idx & 3;
                cpasync16(bd + row * 80 + seg * 16,
                          LB + (size_t)row * D + d0 + seg * 8);
            }
        }
        asm volatile("cp.async.commit_group;" ::: "memory");

        // prefetch A(c+1) globals
        float4 pa[4];
        const int d0n = e0 + (c + 1) * 32;
        if (c + 1 < nc) {
#pragma unroll
            for (int it = 0; it < 4; ++it) {
                const int idx = it * 256 + tid;
                const int row = idx >> 3, seg = idx & 7;
                pa[it] = *(const float4*)&X[(size_t)(b0 + row) * D + d0n + seg * 4];
            }
        }

        // ---- compute chunk c (fp16 m16n8k16, 2 k-steps of 16)
        const uint32_t aB = aFrag + (c & 1) * ABUF;
        const uint32_t bB = bFrag + (c % 3) * BBUF;
#pragma unroll
        for (int ks = 0; ks < 2; ++ks) {
            uint32_t a[2][4], b[8][2];
#pragma unroll
            for (int mt = 0; mt < 2; ++mt) {
                const uint32_t base = aB + mt * (16 * 80) + ks * 32;
                a[mt][0] = ldsf(base);
                a[mt][1] = ldsf(base + 8 * 80);
                a[mt][2] = ldsf(base + 16);
                a[mt][3] = ldsf(base + 8 * 80 + 16);
            }
#pragma unroll
            for (int nt = 0; nt < 8; ++nt) {
                const uint32_t base = bB + nt * (8 * 80) + ks * 32;
                b[nt][0] = ldsf(base);
                b[nt][1] = ldsf(base + 16);
            }
#pragma unroll
            for (int mt = 0; mt < 2; ++mt)
#pragma unroll
                for (int nt = 0; nt < 8; ++nt)
                    asm volatile(
                        "mma.sync.aligned.m16n8k16.row.col.f32.f16.f16.f32 "
                        "{%0,%1,%2,%3},{%4,%5,%6,%7},{%8,%9},{%0,%1,%2,%3};"
                        : "+f"(acc[mt][nt][0]), "+f"(acc[mt][nt][1]),
                          "+f"(acc[mt][nt][2]), "+f"(acc[mt][nt][3])
                        : "r"(a[mt][0]), "r"(a[mt][1]), "r"(a[mt][2]), "r"(a[mt][3]),
                          "r"(b[nt][0]), "r"(b[nt][1]));
        }

        // store A(c+1) (other buffer)
        if (c + 1 < nc) {
#pragma unroll
            for (int it = 0; it < 4; ++it) {
                const int idx = it * 256 + tid;
                const int row = idx >> 3, seg = idx & 7;
                float4 wv = *(const float4*)&Wsm[d0n + seg * 4];
                __half2 h0 = __floats2half2_rn(pa[it].x - wv.x, pa[it].y - wv.y);
                __half2 h1 = __floats2half2_rn(pa[it].z - wv.z, pa[it].w - wv.w);
                uint2 u = make_uint2(*(uint32_t*)&h0, *(uint32_t*)&h1);
                *(uint2*)(smem + AOFF + ((c + 1) & 1) * ABUF + row * 80 + seg * 8) = u;
            }
        }
    }

    // ---- epilogue: per-row sum of squares
    float q[4];
#pragma unroll
    for (int mt = 0; mt < 2; ++mt) {
        float s0 = 0.f, s1 = 0.f;
#pragma unroll
        for (int nt = 0; nt < 8; ++nt) {
            s0 += acc[mt][nt][0] * acc[mt][nt][0] + acc[mt][nt][1] * acc[mt][nt][1];
            s1 += acc[mt][nt][2] * acc[mt][nt][2] + acc[mt][nt][3] * acc[mt][nt][3];
        }
        q[mt * 2 + 0] = s0;   // row m0 + 16*mt + gq
        q[mt * 2 + 1] = s1;   // row m0 + 16*mt + gq + 8
    }
#pragma unroll
    for (int i = 0; i < 4; ++i) {
        q[i] += __shfl_xor_sync(0xffffffffu, q[i], 1);
        q[i] += __shfl_xor_sync(0xffffffffu, q[i], 2);
    }
    float* red = (float*)(smem + ROFF);
    __syncthreads();
    if (tg == 0) {
        const int wn = wid >> 2;
        const int rr = m0 + gq;
        red[wn * 128 + rr +  0] = q[0];
        red[wn * 128 + rr +  8] = q[1];
        red[wn * 128 + rr + 16] = q[2];
        red[wn * 128 + rr + 24] = q[3];
    }
    __syncthreads();
    if (tid < 128) {
        float s = red[tid] + red[128 + tid];
        g_part[((size_t)j * 1024 + b0 + tid) * KC + k] = s;
    }
}

// ---------------------------------------------------------------------------
__global__ void finalize(float* __restrict__ out) {
    const size_t idx = (size_t)blockIdx.x * 256 + threadIdx.x;  // 1024*256
    float s = g_part[idx] + g_part[262144 + idx] +
              g_part[2 * 262144 + idx] + g_part[3 * 262144 + idx];
    out[idx] = sqrtf(s);
}

// ---------------------------------------------------------------------------
extern "C" void kernel_launch(void* const* d_in, const int* in_sizes, int n_in,
                              void* d_out, int out_size) {
    const float* X     = (const float*)d_in[0];  // [1024, 512]
    const float* W     = (const float*)d_in[1];  // [256, 1, 512]
    const float* diags = (const float*)d_in[2];  // [256, 512]
    const float* lower = (const float*)d_in[3];  // [256, 130816]
    float* out = (float*)d_out;                  // [1024, 256]

    build_LTh<<<dim3(KC, 40), 256>>>(diags, lower);

    cudaFuncSetAttribute(gml2_mma, cudaFuncAttributeMaxDynamicSharedMemorySize,
                         SMEMSZ);
    dim3 grid(8, KC, 4);
    gml2_mma<<<grid, 256, SMEMSZ>>>(X, W);

    finalize<<<1024, 256>>>(out);
}